// round 15
// baseline (speedup 1.0000x reference)
#include <cuda_runtime.h>
#include <cuda_bf16.h>

// ---------------------------------------------------------------------------
// CascadedAttention: B=128, T=75, D=512, V=28
//
// Prologue (3xTF32 tensor cores, v2):
//   prep_w : W^T = [Ua | gk | Co | 0pad] as [n][k], k-interleaved -> g_WtI
//            + fused bias vector (Ba2 | gbias0 | 0)  (B-fragment = 1 LDG.64)
//   gemm   : [9600,512] @ [512,640] -> g_scr, m16n8k8 tf32, 3-pass split.
//            A loaded DIRECTLY from x (2x LDG.32 per row-pair; prep_x removed)
//            __launch_bounds__(256) only -> no forced reg cap, no spills.
// Recurrence: R4/R7 known-good + B-phase 2-row interleave (only change).
// ---------------------------------------------------------------------------

#define B_   128
#define T_   75
#define D_   512
#define V_   28
#define NCp  640               // padded scratch row (624 used + 16 pad)
#define PT   (T_*NCp)          // 48000 floats per batch row
#define M_   (B_*T_)           // 9600 flat rows

__device__ float g_scr[M_ * NCp];     // 24.6 MB
__device__ float g_WtI[NCp * D_];     // 1.31 MB  (transposed+interleaved W)
__device__ float g_bias[NCp];

__device__ __forceinline__ float ex2f(float x){ float y; asm("ex2.approx.f32 %0, %1;" : "=f"(y) : "f"(x)); return y; }
__device__ __forceinline__ float rcpf(float x){ float y; asm("rcp.approx.f32 %0, %1;" : "=f"(y) : "f"(x)); return y; }
__device__ __forceinline__ float tanhf_hw(float x){ float y; asm("tanh.approx.f32 %0, %1;" : "=f"(y) : "f"(x)); return y; }
#define L2E 1.4426950408889634f
__device__ __forceinline__ float fast_sig(float x){ return fmaf(0.5f, tanhf_hw(0.5f * x), 0.5f); }

// tf32 split: hi = rna-rounded tf32, lo = residual
__device__ __forceinline__ void split_tf32(float x, unsigned& hi, unsigned& lo){
    unsigned h; asm("cvt.rna.tf32.f32 %0, %1;" : "=r"(h) : "f"(x));
    hi = h;
    lo = __float_as_uint(x - __uint_as_float(h));
}

__device__ __forceinline__ void mma_tf32(float* d,
    unsigned a0, unsigned a1, unsigned a2, unsigned a3,
    unsigned b0, unsigned b1)
{
    asm volatile(
        "mma.sync.aligned.m16n8k8.row.col.f32.tf32.tf32.f32 "
        "{%0,%1,%2,%3}, {%4,%5,%6,%7}, {%8,%9}, {%0,%1,%2,%3};"
        : "+f"(d[0]), "+f"(d[1]), "+f"(d[2]), "+f"(d[3])
        : "r"(a0), "r"(a1), "r"(a2), "r"(a3), "r"(b0), "r"(b1));
}

// interleave map within each 8-elem k-group (B side only)
__device__ __forceinline__ int kmap(int o){
    return (o & ~7) + ((o >> 1) & 3) + ((o & 1) << 2);
}

// ---------------------------------------------------------------------------
// prep_w: g_WtI[n][o] = W[kmap(o)][n],  W = [Ua | gk | Co | 0]; + g_bias.
// grid 640 x 512 threads.
// ---------------------------------------------------------------------------
__global__ void __launch_bounds__(512)
prep_w_kernel(const float* __restrict__ Ua,
              const float* __restrict__ gk,
              const float* __restrict__ Co,
              const float* __restrict__ Ba2,
              const float* __restrict__ gbias)
{
    int n = blockIdx.x;
    int o = threadIdx.x;
    int k = kmap(o);
    float v = 0.0f;
    if (n < 512)      v = Ua[k * 512 + n];
    else if (n < 596) v = gk[k * 84 + (n - 512)];
    else if (n < 624) v = Co[k * 28 + (n - 596)];
    g_WtI[n * D_ + o] = v;
    if (o == 0) {
        float bv = 0.0f;
        if (n < 512)      bv = Ba2[n];
        else if (n < 596) bv = gbias[n - 512];
        g_bias[n] = bv;
    }
}

// ---------------------------------------------------------------------------
// gemm: grid (150, 2), 256 threads = 8 warps (2 M x 4 N).
// Warp tile 32x80: 2 m16-frags x 10 n8-frags, K=512 in 64 k8 steps, 3xTF32.
// A read directly from x (row-major): per row, k = ko+tg and ko+tg+4.
// ---------------------------------------------------------------------------
__global__ void __launch_bounds__(256)
gemm_kernel(const float* __restrict__ x)
{
    const int lane = threadIdx.x & 31;
    const int w    = threadIdx.x >> 5;
    const int g    = lane >> 2;          // groupID
    const int tg   = lane & 3;           // threadID_in_group
    const int mw   = w & 1;
    const int nw   = w >> 1;
    const int m0   = blockIdx.x * 64 + mw * 32;
    const int n0   = blockIdx.y * 320 + nw * 80;

    const float* Ap = x + (long)(m0 + g) * D_ + tg;      // +0 / +4 per frag k
    const float* Bp = g_WtI + (long)(n0 + g) * D_ + tg * 2;

    float acc[20][4];
    #pragma unroll
    for (int f = 0; f < 20; f++) {
        acc[f][0] = 0.f; acc[f][1] = 0.f; acc[f][2] = 0.f; acc[f][3] = 0.f;
    }

    for (int ko = 0; ko < D_; ko += 8) {
        // A rows g, g+8, g+16, g+24; k = ko+tg (lo) and ko+tg+4 (hi)
        unsigned ah[8], al[8];
        {
            const float* a0p = Ap + ko;
            float v0 = a0p[0],          v1 = a0p[4];
            float v2 = a0p[ 8*D_],      v3 = a0p[ 8*D_ + 4];
            float v4 = a0p[16*D_],      v5 = a0p[16*D_ + 4];
            float v6 = a0p[24*D_],      v7 = a0p[24*D_ + 4];
            split_tf32(v0, ah[0], al[0]); split_tf32(v1, ah[1], al[1]);
            split_tf32(v2, ah[2], al[2]); split_tf32(v3, ah[3], al[3]);
            split_tf32(v4, ah[4], al[4]); split_tf32(v5, ah[5], al[5]);
            split_tf32(v6, ah[6], al[6]); split_tf32(v7, ah[7], al[7]);
        }

        #pragma unroll
        for (int nt = 0; nt < 10; nt++) {
            float2 b = *reinterpret_cast<const float2*>(Bp + nt * 8 * D_ + ko);
            unsigned bh0, bl0, bh1, bl1;
            split_tf32(b.x, bh0, bl0);
            split_tf32(b.y, bh1, bl1);
            // m-half 0: a-frag (a0,a1,a2,a3) = (row g k lo, row g+8 k lo, row g k hi, row g+8 k hi)
            mma_tf32(acc[nt],      ah[0], ah[2], ah[1], ah[3], bh0, bh1);
            mma_tf32(acc[nt],      ah[0], ah[2], ah[1], ah[3], bl0, bl1);
            mma_tf32(acc[nt],      al[0], al[2], al[1], al[3], bh0, bh1);
            // m-half 1
            mma_tf32(acc[10 + nt], ah[4], ah[6], ah[5], ah[7], bh0, bh1);
            mma_tf32(acc[10 + nt], ah[4], ah[6], ah[5], ah[7], bl0, bl1);
            mma_tf32(acc[10 + nt], al[4], al[6], al[5], al[7], bh0, bh1);
        }
    }

    // epilogue: D rows (g, g+8, g+16, g+24), cols tg*2, tg*2+1 per n-frag
    #pragma unroll
    for (int nt = 0; nt < 10; nt++) {
        const int col = n0 + nt * 8 + tg * 2;
        float2 bs = *reinterpret_cast<const float2*>(g_bias + col);
        const long r0 = m0 + g;
        float2 v;
        v.x = acc[nt][0] + bs.x;      v.y = acc[nt][1] + bs.y;
        *reinterpret_cast<float2*>(g_scr + r0 * NCp + col) = v;
        v.x = acc[nt][2] + bs.x;      v.y = acc[nt][3] + bs.y;
        *reinterpret_cast<float2*>(g_scr + (r0 + 8) * NCp + col) = v;
        v.x = acc[10 + nt][0] + bs.x; v.y = acc[10 + nt][1] + bs.y;
        *reinterpret_cast<float2*>(g_scr + (r0 + 16) * NCp + col) = v;
        v.x = acc[10 + nt][2] + bs.x; v.y = acc[10 + nt][3] + bs.y;
        *reinterpret_cast<float2*>(g_scr + (r0 + 24) * NCp + col) = v;
    }
}

// ---------------------------------------------------------------------------
// Recurrence kernel: R4/R7 known-good + B-phase 2-row interleave (only change).
// 128 CTAs x 576 threads.
// ---------------------------------------------------------------------------
#define SMEM_FLOATS 56928
#define NTH 576

__global__ void __launch_bounds__(NTH)
recur_kernel(const float* __restrict__ Wa,
             const float* __restrict__ Va,
             const float* __restrict__ Ba1,
             const float* __restrict__ grk,
             const float* __restrict__ gbias,
             const float* __restrict__ Wo,
             const float* __restrict__ Uo,
             const float* __restrict__ Bo,
             const float* __restrict__ emb,
             float* __restrict__ out)
{
    extern __shared__ float smem[];
    float*        uah  = smem;                 // [75][512]
    float*        xgc  = smem + 38400;         // [75][112]
    unsigned int* wab  = reinterpret_cast<unsigned int*>(smem + 46800); // [28][256] bf16x2
    float*        va_s = smem + 53968;
    float*        ba1_s= smem + 54480;
    float*        uo_s = smem + 54992;
    float*        was_s= smem + 55776;
    float*        sc_s = smem + 56288;
    float*        xmc_s= smem + 56448;
    float*        hm_s = smem + 56560;
    float*        st_s = smem + 56648;
    float*        pr_s = smem + 56680;
    float*        woy_s= smem + 56712;
    float*        uoh_s= smem + 56744;
    float*        lut_s= smem + 56776;
    float*        b1_s = smem + 56808;
    float*        bo_s = smem + 56896;

    const int tid  = threadIdx.x;
    const int b    = blockIdx.x;
    const int lane = tid & 31;
    const int wid  = tid >> 5;

    // ---- bulk load precomputed UaH / XGC from scratch (stride 640, skip pad) ----
    const float4* src = reinterpret_cast<const float4*>(g_scr + (long)b * PT);
    for (int i = tid; i < PT/4; i += NTH) {
        float4 v = src[i];
        int base = i * 4;
        int t = base / NCp;
        int c = base - t * NCp;
        if (c < 512)      *reinterpret_cast<float4*>(&uah[t * 512 + c]) = v;
        else if (c < 624) *reinterpret_cast<float4*>(&xgc[t * 112 + (c - 512)]) = v;
    }
    // ---- params ----
    for (int i = tid; i < 512; i += NTH) { va_s[i] = Va[i]; ba1_s[i] = Ba1[i]; }
    for (int i = tid; i < 784; i += NTH) uo_s[i] = Uo[i];
    for (int i = tid; i < 28*256; i += NTH) {
        int r = i >> 8, c = i & 255;
        __nv_bfloat162 h;
        h.x = __float2bfloat16_rn(Wa[r * 512 + 2*c]);
        h.y = __float2bfloat16_rn(Wa[r * 512 + 2*c + 1]);
        wab[i] = *reinterpret_cast<unsigned int*>(&h);
    }
    if (tid < 84) b1_s[tid] = gbias[84 + tid];
    if (tid < 28) {
        bo_s[tid] = Bo[tid];
        float a = 0.0f;
        #pragma unroll
        for (int j = 0; j < 28; j++) a = fmaf(emb[tid * 28 + j], Wo[j], a);
        lut_s[tid] = a;
    }
    if (tid < 32) { st_s[tid] = 0.0f; pr_s[tid] = 0.0f; }
    __syncthreads();

    float va_r[16];
    #pragma unroll
    for (int i = 0; i < 16; i++) va_r[i] = va_s[lane + 32*i];

    float* outb = out + (long)b * T_ * V_;

    for (int t = 0; t < T_; t++) {
        // ---------- Phase A: state-only GEMVs, all in parallel ----------
        if (tid < 256) {
            float2 a = *reinterpret_cast<const float2*>(&ba1_s[2*tid]);
            #pragma unroll
            for (int v = 0; v < 28; v++) {
                float s = st_s[v];
                unsigned int w = wab[v * 256 + tid];
                float wx = __int_as_float(w << 16);
                float wy = __int_as_float(w & 0xffff0000u);
                a.x = fmaf(s, wx, a.x);
                a.y = fmaf(s, wy, a.y);
            }
            *reinterpret_cast<float2*>(&was_s[2*tid]) = a;
        } else if (tid < 340) {
            int g = tid - 256;              // hm: 84 outputs
            float a = b1_s[g];
            #pragma unroll
            for (int v = 0; v < 28; v++) a = fmaf(st_s[v], grk[v * 84 + g], a);
            hm_s[g] = a;
        } else if (wid == 11) {
            if (lane < 28) {                // uoh
                float a = 0.0f;
                #pragma unroll
                for (int u = 0; u < 28; u++) a = fmaf(st_s[u], uo_s[u * 28 + lane], a);
                uoh_s[lane] = a;
            }
        } else if (wid == 12) {
            if (lane < 28) {                // woy (embedding LUT on int(prev_pred))
                int ix = (int)pr_s[lane];
                ix = max(0, min(27, ix));
                woy_s[lane] = lut_s[ix];
            }
        }
        __syncthreads();

        // ---------- Phase B: scores, 18 warps, 2-row interleave ----------
        {
            float ws_r[16];
            #pragma unroll
            for (int i = 0; i < 16; i++) ws_r[i] = was_s[lane + 32*i];

            for (int p = wid; p < T_; p += 36) {
                const int rB = p + 18;
                const bool hasB = (rB < T_);
                const float* uA = &uah[p * 512];
                const float* uB = &uah[(hasB ? rB : p) * 512];
                float aA0 = 0.f, aA1 = 0.f, aB0 = 0.f, aB1 = 0.f;
                #pragma unroll
                for (int i = 0; i < 16; i += 2) {
                    float tA0 = tanhf_hw(uA[lane + 32*i]     + ws_r[i]);
                    float tB0 = tanhf_hw(uB[lane + 32*i]     + ws_r[i]);
                    float tA1 = tanhf_hw(uA[lane + 32*(i+1)] + ws_r[i+1]);
                    float tB1 = tanhf_hw(uB[lane + 32*(i+1)] + ws_r[i+1]);
                    aA0 = fmaf(tA0, va_r[i],   aA0);
                    aB0 = fmaf(tB0, va_r[i],   aB0);
                    aA1 = fmaf(tA1, va_r[i+1], aA1);
                    aB1 = fmaf(tB1, va_r[i+1], aB1);
                }
                float accA = aA0 + aA1;
                float accB = aB0 + aB1;
                #pragma unroll
                for (int o = 16; o; o >>= 1) {
                    accA += __shfl_xor_sync(0xffffffffu, accA, o);
                    accB += __shfl_xor_sync(0xffffffffu, accB, o);
                }
                if (lane == 0) {
                    sc_s[p] = accA;
                    if (hasB) sc_s[rB] = accB;
                }
            }
        }
        __syncthreads();

        // ---------- Phase C: softmax-in-registers + sm.XGC (warps 0-3) ----------
        if (wid < 4) {
            float s0 = sc_s[lane];
            float s1 = sc_s[lane + 32];
            float s2 = (lane < 11) ? sc_s[lane + 64] : -3.0e38f;
            float m = fmaxf(fmaxf(s0, s1), s2);
            #pragma unroll
            for (int o = 16; o; o >>= 1) m = fmaxf(m, __shfl_xor_sync(0xffffffffu, m, o));
            float e0 = ex2f((s0 - m) * L2E);
            float e1 = ex2f((s1 - m) * L2E);
            float e2 = (lane < 11) ? ex2f((s2 - m) * L2E) : 0.0f;
            float sum = e0 + e1 + e2;
            #pragma unroll
            for (int o = 16; o; o >>= 1) sum += __shfl_xor_sync(0xffffffffu, sum, o);
            float inv = rcpf(sum);

            int c = wid * 28 + ((lane < 28) ? lane : 0);   // 112 cols; lanes 28-31 duplicate
            float a0 = 0.0f, a1 = 0.0f, a2 = 0.0f, a3 = 0.0f;
            #pragma unroll
            for (int k = 0; k < 75; k += 4) {
                float w0 = __shfl_sync(0xffffffffu, (k      < 32) ? e0 : ((k      < 64) ? e1 : e2), k      & 31);
                a0 = fmaf(w0, xgc[k * 112 + c], a0);
                if (k + 1 < 75) {
                    float w1 = __shfl_sync(0xffffffffu, (k+1 < 32) ? e0 : ((k+1 < 64) ? e1 : e2), (k+1) & 31);
                    a1 = fmaf(w1, xgc[(k+1) * 112 + c], a1);
                }
                if (k + 2 < 75) {
                    float w2 = __shfl_sync(0xffffffffu, (k+2 < 32) ? e0 : ((k+2 < 64) ? e1 : e2), (k+2) & 31);
                    a2 = fmaf(w2, xgc[(k+2) * 112 + c], a2);
                }
                if (k + 3 < 75) {
                    float w3 = __shfl_sync(0xffffffffu, (k+3 < 32) ? e0 : ((k+3 < 64) ? e1 : e2), (k+3) & 31);
                    a3 = fmaf(w3, xgc[(k+3) * 112 + c], a3);
                }
            }
            if (lane < 28) xmc_s[c] = ((a0 + a1) + (a2 + a3)) * inv;
        }
        __syncthreads();

        // ---------- Phase D: GRU gates + output softmax (warp 0) ----------
        if (wid == 0) {
            int v = lane;
            float logit = -3.0e38f;
            float ns = 0.0f;
            if (v < 28) {
                float xz = xmc_s[v],      xr = xmc_s[28 + v], xh  = xmc_s[56 + v];
                float hz = hm_s[v],       hr = hm_s[28 + v],  hh_ = hm_s[56 + v];
                float z  = fast_sig(xz + hz);
                float r  = fast_sig(xr + hr);
                float hh = tanhf_hw(fmaf(r, hh_, xh));
                float st = st_s[v];
                ns = fmaf(z, st - hh, hh);
                logit = ((woy_s[v] + uoh_s[v]) + (xmc_s[84 + v] + bo_s[v]));
            }
            float m = logit;
            #pragma unroll
            for (int o = 16; o; o >>= 1) m = fmaxf(m, __shfl_xor_sync(0xffffffffu, m, o));
            float e = (v < 28) ? ex2f((logit - m) * L2E) : 0.0f;
            float sum = e;
            #pragma unroll
            for (int o = 16; o; o >>= 1) sum += __shfl_xor_sync(0xffffffffu, sum, o);
            float p = e * rcpf(sum);
            if (v < 28) {
                st_s[v] = ns;
                pr_s[v] = p;
                outb[t * V_ + v] = p;
            }
        }
        __syncthreads();
    }
}

// ---------------------------------------------------------------------------
extern "C" void kernel_launch(void* const* d_in, const int* in_sizes, int n_in,
                              void* d_out, int out_size)
{
    const float* x    = (const float*)d_in[0];
    const float* Wa   = (const float*)d_in[1];
    const float* Ua   = (const float*)d_in[2];
    const float* Va   = (const float*)d_in[3];
    const float* Ba1  = (const float*)d_in[4];
    const float* Ba2  = (const float*)d_in[5];
    /* Ba3 (d_in[6]) is softmax-invariant: skipped */
    const float* gk   = (const float*)d_in[7];
    const float* grk  = (const float*)d_in[8];
    const float* gb   = (const float*)d_in[9];
    const float* Wo   = (const float*)d_in[10];
    const float* Uo   = (const float*)d_in[11];
    const float* Co   = (const float*)d_in[12];
    const float* Bo   = (const float*)d_in[13];
    const float* emb  = (const float*)d_in[14];
    float* out = (float*)d_out;

    cudaFuncSetAttribute(recur_kernel, cudaFuncAttributeMaxDynamicSharedMemorySize, SMEM_FLOATS * 4);

    prep_w_kernel<<<NCp, 512>>>(Ua, gk, Co, Ba2, gb);
    gemm_kernel<<<dim3(150, 2), 256>>>(x);
    recur_kernel<<<B_, NTH, SMEM_FLOATS * 4>>>(Wa, Va, Ba1, grk, gb, Wo, Uo, Bo, emb, out);
}

// round 16
// speedup vs baseline: 1.0337x; 1.0337x over previous
#include <cuda_runtime.h>
#include <cuda_bf16.h>

// ---------------------------------------------------------------------------
// CascadedAttention: B=128, T=75, D=512, V=28
//
// Prologue (3xTF32 tensor cores, v2 -- R15's version, kept):
//   prep_w : W^T = [Ua | gk | Co | 0pad] as [n][k], k-interleaved -> g_WtI
//            + fused bias vector (Ba2 | gbias0 | 0)
//   gemm   : [9600,512] @ [512,640] -> g_scr, m16n8k8 tf32, 3-pass split.
//            A loaded directly from x; __launch_bounds__(256), uncapped regs.
// Recurrence: EXACT R4/R7/R13 known-good kernel (no interleave -- reverted).
// ---------------------------------------------------------------------------

#define B_   128
#define T_   75
#define D_   512
#define V_   28
#define NCp  640               // padded scratch row (624 used + 16 pad)
#define PT   (T_*NCp)          // 48000 floats per batch row
#define M_   (B_*T_)           // 9600 flat rows

__device__ float g_scr[M_ * NCp];     // 24.6 MB
__device__ float g_WtI[NCp * D_];     // 1.31 MB  (transposed+interleaved W)
__device__ float g_bias[NCp];

__device__ __forceinline__ float ex2f(float x){ float y; asm("ex2.approx.f32 %0, %1;" : "=f"(y) : "f"(x)); return y; }
__device__ __forceinline__ float rcpf(float x){ float y; asm("rcp.approx.f32 %0, %1;" : "=f"(y) : "f"(x)); return y; }
__device__ __forceinline__ float tanhf_hw(float x){ float y; asm("tanh.approx.f32 %0, %1;" : "=f"(y) : "f"(x)); return y; }
#define L2E 1.4426950408889634f
__device__ __forceinline__ float fast_sig(float x){ return fmaf(0.5f, tanhf_hw(0.5f * x), 0.5f); }

// tf32 split: hi = rna-rounded tf32, lo = residual
__device__ __forceinline__ void split_tf32(float x, unsigned& hi, unsigned& lo){
    unsigned h; asm("cvt.rna.tf32.f32 %0, %1;" : "=r"(h) : "f"(x));
    hi = h;
    lo = __float_as_uint(x - __uint_as_float(h));
}

__device__ __forceinline__ void mma_tf32(float* d,
    unsigned a0, unsigned a1, unsigned a2, unsigned a3,
    unsigned b0, unsigned b1)
{
    asm volatile(
        "mma.sync.aligned.m16n8k8.row.col.f32.tf32.tf32.f32 "
        "{%0,%1,%2,%3}, {%4,%5,%6,%7}, {%8,%9}, {%0,%1,%2,%3};"
        : "+f"(d[0]), "+f"(d[1]), "+f"(d[2]), "+f"(d[3])
        : "r"(a0), "r"(a1), "r"(a2), "r"(a3), "r"(b0), "r"(b1));
}

// interleave map within each 8-elem k-group (B side only)
__device__ __forceinline__ int kmap(int o){
    return (o & ~7) + ((o >> 1) & 3) + ((o & 1) << 2);
}

// ---------------------------------------------------------------------------
// prep_w: g_WtI[n][o] = W[kmap(o)][n],  W = [Ua | gk | Co | 0]; + g_bias.
// grid 640 x 512 threads.
// ---------------------------------------------------------------------------
__global__ void __launch_bounds__(512)
prep_w_kernel(const float* __restrict__ Ua,
              const float* __restrict__ gk,
              const float* __restrict__ Co,
              const float* __restrict__ Ba2,
              const float* __restrict__ gbias)
{
    int n = blockIdx.x;
    int o = threadIdx.x;
    int k = kmap(o);
    float v = 0.0f;
    if (n < 512)      v = Ua[k * 512 + n];
    else if (n < 596) v = gk[k * 84 + (n - 512)];
    else if (n < 624) v = Co[k * 28 + (n - 596)];
    g_WtI[n * D_ + o] = v;
    if (o == 0) {
        float bv = 0.0f;
        if (n < 512)      bv = Ba2[n];
        else if (n < 596) bv = gbias[n - 512];
        g_bias[n] = bv;
    }
}

// ---------------------------------------------------------------------------
// gemm: grid (150, 2), 256 threads = 8 warps (2 M x 4 N).
// Warp tile 32x80: 2 m16-frags x 10 n8-frags, K=512 in 64 k8 steps, 3xTF32.
// A read directly from x (row-major): per row, k = ko+tg and ko+tg+4.
// ---------------------------------------------------------------------------
__global__ void __launch_bounds__(256)
gemm_kernel(const float* __restrict__ x)
{
    const int lane = threadIdx.x & 31;
    const int w    = threadIdx.x >> 5;
    const int g    = lane >> 2;          // groupID
    const int tg   = lane & 3;           // threadID_in_group
    const int mw   = w & 1;
    const int nw   = w >> 1;
    const int m0   = blockIdx.x * 64 + mw * 32;
    const int n0   = blockIdx.y * 320 + nw * 80;

    const float* Ap = x + (long)(m0 + g) * D_ + tg;      // +0 / +4 per frag k
    const float* Bp = g_WtI + (long)(n0 + g) * D_ + tg * 2;

    float acc[20][4];
    #pragma unroll
    for (int f = 0; f < 20; f++) {
        acc[f][0] = 0.f; acc[f][1] = 0.f; acc[f][2] = 0.f; acc[f][3] = 0.f;
    }

    for (int ko = 0; ko < D_; ko += 8) {
        // A rows g, g+8, g+16, g+24; k = ko+tg (lo) and ko+tg+4 (hi)
        unsigned ah[8], al[8];
        {
            const float* a0p = Ap + ko;
            float v0 = a0p[0],          v1 = a0p[4];
            float v2 = a0p[ 8*D_],      v3 = a0p[ 8*D_ + 4];
            float v4 = a0p[16*D_],      v5 = a0p[16*D_ + 4];
            float v6 = a0p[24*D_],      v7 = a0p[24*D_ + 4];
            split_tf32(v0, ah[0], al[0]); split_tf32(v1, ah[1], al[1]);
            split_tf32(v2, ah[2], al[2]); split_tf32(v3, ah[3], al[3]);
            split_tf32(v4, ah[4], al[4]); split_tf32(v5, ah[5], al[5]);
            split_tf32(v6, ah[6], al[6]); split_tf32(v7, ah[7], al[7]);
        }

        #pragma unroll
        for (int nt = 0; nt < 10; nt++) {
            float2 b = *reinterpret_cast<const float2*>(Bp + nt * 8 * D_ + ko);
            unsigned bh0, bl0, bh1, bl1;
            split_tf32(b.x, bh0, bl0);
            split_tf32(b.y, bh1, bl1);
            // m-half 0
            mma_tf32(acc[nt],      ah[0], ah[2], ah[1], ah[3], bh0, bh1);
            mma_tf32(acc[nt],      ah[0], ah[2], ah[1], ah[3], bl0, bl1);
            mma_tf32(acc[nt],      al[0], al[2], al[1], al[3], bh0, bh1);
            // m-half 1
            mma_tf32(acc[10 + nt], ah[4], ah[6], ah[5], ah[7], bh0, bh1);
            mma_tf32(acc[10 + nt], ah[4], ah[6], ah[5], ah[7], bl0, bl1);
            mma_tf32(acc[10 + nt], al[4], al[6], al[5], al[7], bh0, bh1);
        }
    }

    // epilogue: D rows (g, g+8, g+16, g+24), cols tg*2, tg*2+1 per n-frag
    #pragma unroll
    for (int nt = 0; nt < 10; nt++) {
        const int col = n0 + nt * 8 + tg * 2;
        float2 bs = *reinterpret_cast<const float2*>(g_bias + col);
        const long r0 = m0 + g;
        float2 v;
        v.x = acc[nt][0] + bs.x;      v.y = acc[nt][1] + bs.y;
        *reinterpret_cast<float2*>(g_scr + r0 * NCp + col) = v;
        v.x = acc[nt][2] + bs.x;      v.y = acc[nt][3] + bs.y;
        *reinterpret_cast<float2*>(g_scr + (r0 + 8) * NCp + col) = v;
        v.x = acc[10 + nt][0] + bs.x; v.y = acc[10 + nt][1] + bs.y;
        *reinterpret_cast<float2*>(g_scr + (r0 + 16) * NCp + col) = v;
        v.x = acc[10 + nt][2] + bs.x; v.y = acc[10 + nt][3] + bs.y;
        *reinterpret_cast<float2*>(g_scr + (r0 + 24) * NCp + col) = v;
    }
}

// ---------------------------------------------------------------------------
// Recurrence kernel (EXACT R4/R7/R13 known-good): 128 CTAs x 576 threads.
// ---------------------------------------------------------------------------
#define SMEM_FLOATS 56928
#define NTH 576

__global__ void __launch_bounds__(NTH)
recur_kernel(const float* __restrict__ Wa,
             const float* __restrict__ Va,
             const float* __restrict__ Ba1,
             const float* __restrict__ grk,
             const float* __restrict__ gbias,
             const float* __restrict__ Wo,
             const float* __restrict__ Uo,
             const float* __restrict__ Bo,
             const float* __restrict__ emb,
             float* __restrict__ out)
{
    extern __shared__ float smem[];
    float*        uah  = smem;                 // [75][512]
    float*        xgc  = smem + 38400;         // [75][112]
    unsigned int* wab  = reinterpret_cast<unsigned int*>(smem + 46800); // [28][256] bf16x2
    float*        va_s = smem + 53968;
    float*        ba1_s= smem + 54480;
    float*        uo_s = smem + 54992;
    float*        was_s= smem + 55776;
    float*        sc_s = smem + 56288;
    float*        xmc_s= smem + 56448;
    float*        hm_s = smem + 56560;
    float*        st_s = smem + 56648;
    float*        pr_s = smem + 56680;
    float*        woy_s= smem + 56712;
    float*        uoh_s= smem + 56744;
    float*        lut_s= smem + 56776;
    float*        b1_s = smem + 56808;
    float*        bo_s = smem + 56896;

    const int tid  = threadIdx.x;
    const int b    = blockIdx.x;
    const int lane = tid & 31;
    const int wid  = tid >> 5;

    // ---- bulk load precomputed UaH / XGC from scratch (stride 640, skip pad) ----
    const float4* src = reinterpret_cast<const float4*>(g_scr + (long)b * PT);
    for (int i = tid; i < PT/4; i += NTH) {
        float4 v = src[i];
        int base = i * 4;
        int t = base / NCp;
        int c = base - t * NCp;
        if (c < 512)      *reinterpret_cast<float4*>(&uah[t * 512 + c]) = v;
        else if (c < 624) *reinterpret_cast<float4*>(&xgc[t * 112 + (c - 512)]) = v;
    }
    // ---- params ----
    for (int i = tid; i < 512; i += NTH) { va_s[i] = Va[i]; ba1_s[i] = Ba1[i]; }
    for (int i = tid; i < 784; i += NTH) uo_s[i] = Uo[i];
    for (int i = tid; i < 28*256; i += NTH) {
        int r = i >> 8, c = i & 255;
        __nv_bfloat162 h;
        h.x = __float2bfloat16_rn(Wa[r * 512 + 2*c]);
        h.y = __float2bfloat16_rn(Wa[r * 512 + 2*c + 1]);
        wab[i] = *reinterpret_cast<unsigned int*>(&h);
    }
    if (tid < 84) b1_s[tid] = gbias[84 + tid];
    if (tid < 28) {
        bo_s[tid] = Bo[tid];
        float a = 0.0f;
        #pragma unroll
        for (int j = 0; j < 28; j++) a = fmaf(emb[tid * 28 + j], Wo[j], a);
        lut_s[tid] = a;
    }
    if (tid < 32) { st_s[tid] = 0.0f; pr_s[tid] = 0.0f; }
    __syncthreads();

    float va_r[16];
    #pragma unroll
    for (int i = 0; i < 16; i++) va_r[i] = va_s[lane + 32*i];

    float* outb = out + (long)b * T_ * V_;

    for (int t = 0; t < T_; t++) {
        // ---------- Phase A: state-only GEMVs, all in parallel ----------
        if (tid < 256) {
            float2 a = *reinterpret_cast<const float2*>(&ba1_s[2*tid]);
            #pragma unroll
            for (int v = 0; v < 28; v++) {
                float s = st_s[v];
                unsigned int w = wab[v * 256 + tid];
                float wx = __int_as_float(w << 16);
                float wy = __int_as_float(w & 0xffff0000u);
                a.x = fmaf(s, wx, a.x);
                a.y = fmaf(s, wy, a.y);
            }
            *reinterpret_cast<float2*>(&was_s[2*tid]) = a;
        } else if (tid < 340) {
            int g = tid - 256;              // hm: 84 outputs
            float a = b1_s[g];
            #pragma unroll
            for (int v = 0; v < 28; v++) a = fmaf(st_s[v], grk[v * 84 + g], a);
            hm_s[g] = a;
        } else if (wid == 11) {
            if (lane < 28) {                // uoh
                float a = 0.0f;
                #pragma unroll
                for (int u = 0; u < 28; u++) a = fmaf(st_s[u], uo_s[u * 28 + lane], a);
                uoh_s[lane] = a;
            }
        } else if (wid == 12) {
            if (lane < 28) {                // woy (embedding LUT on int(prev_pred))
                int ix = (int)pr_s[lane];
                ix = max(0, min(27, ix));
                woy_s[lane] = lut_s[ix];
            }
        }
        __syncthreads();

        // ---------- Phase B: scores, 18 warps, tanh.approx ----------
        {
            float ws_r[16];
            #pragma unroll
            for (int i = 0; i < 16; i++) ws_r[i] = was_s[lane + 32*i];

            for (int r = wid; r < T_; r += 18) {
                const float* up = &uah[r * 512];
                float acc0 = 0.0f, acc1 = 0.0f;
                #pragma unroll
                for (int i = 0; i < 16; i += 2) {
                    float th0 = tanhf_hw(up[lane + 32*i]     + ws_r[i]);
                    float th1 = tanhf_hw(up[lane + 32*(i+1)] + ws_r[i+1]);
                    acc0 = fmaf(th0, va_r[i],   acc0);
                    acc1 = fmaf(th1, va_r[i+1], acc1);
                }
                float acc = acc0 + acc1;
                #pragma unroll
                for (int o = 16; o; o >>= 1) acc += __shfl_xor_sync(0xffffffffu, acc, o);
                if (lane == 0) sc_s[r] = acc;
            }
        }
        __syncthreads();

        // ---------- Phase C: softmax-in-registers + sm.XGC (warps 0-3) ----------
        if (wid < 4) {
            float s0 = sc_s[lane];
            float s1 = sc_s[lane + 32];
            float s2 = (lane < 11) ? sc_s[lane + 64] : -3.0e38f;
            float m = fmaxf(fmaxf(s0, s1), s2);
            #pragma unroll
            for (int o = 16; o; o >>= 1) m = fmaxf(m, __shfl_xor_sync(0xffffffffu, m, o));
            float e0 = ex2f((s0 - m) * L2E);
            float e1 = ex2f((s1 - m) * L2E);
            float e2 = (lane < 11) ? ex2f((s2 - m) * L2E) : 0.0f;
            float sum = e0 + e1 + e2;
            #pragma unroll
            for (int o = 16; o; o >>= 1) sum += __shfl_xor_sync(0xffffffffu, sum, o);
            float inv = rcpf(sum);

            int c = wid * 28 + ((lane < 28) ? lane : 0);   // 112 cols; lanes 28-31 duplicate
            float a0 = 0.0f, a1 = 0.0f, a2 = 0.0f, a3 = 0.0f;
            #pragma unroll
            for (int k = 0; k < 75; k += 4) {
                float w0 = __shfl_sync(0xffffffffu, (k      < 32) ? e0 : ((k      < 64) ? e1 : e2), k      & 31);
                a0 = fmaf(w0, xgc[k * 112 + c], a0);
                if (k + 1 < 75) {
                    float w1 = __shfl_sync(0xffffffffu, (k+1 < 32) ? e0 : ((k+1 < 64) ? e1 : e2), (k+1) & 31);
                    a1 = fmaf(w1, xgc[(k+1) * 112 + c], a1);
                }
                if (k + 2 < 75) {
                    float w2 = __shfl_sync(0xffffffffu, (k+2 < 32) ? e0 : ((k+2 < 64) ? e1 : e2), (k+2) & 31);
                    a2 = fmaf(w2, xgc[(k+2) * 112 + c], a2);
                }
                if (k + 3 < 75) {
                    float w3 = __shfl_sync(0xffffffffu, (k+3 < 32) ? e0 : ((k+3 < 64) ? e1 : e2), (k+3) & 31);
                    a3 = fmaf(w3, xgc[(k+3) * 112 + c], a3);
                }
            }
            if (lane < 28) xmc_s[c] = ((a0 + a1) + (a2 + a3)) * inv;
        }
        __syncthreads();

        // ---------- Phase D: GRU gates + output softmax (warp 0) ----------
        if (wid == 0) {
            int v = lane;
            float logit = -3.0e38f;
            float ns = 0.0f;
            if (v < 28) {
                float xz = xmc_s[v],      xr = xmc_s[28 + v], xh  = xmc_s[56 + v];
                float hz = hm_s[v],       hr = hm_s[28 + v],  hh_ = hm_s[56 + v];
                float z  = fast_sig(xz + hz);
                float r  = fast_sig(xr + hr);
                float hh = tanhf_hw(fmaf(r, hh_, xh));
                float st = st_s[v];
                ns = fmaf(z, st - hh, hh);
                logit = ((woy_s[v] + uoh_s[v]) + (xmc_s[84 + v] + bo_s[v]));
            }
            float m = logit;
            #pragma unroll
            for (int o = 16; o; o >>= 1) m = fmaxf(m, __shfl_xor_sync(0xffffffffu, m, o));
            float e = (v < 28) ? ex2f((logit - m) * L2E) : 0.0f;
            float sum = e;
            #pragma unroll
            for (int o = 16; o; o >>= 1) sum += __shfl_xor_sync(0xffffffffu, sum, o);
            float p = e * rcpf(sum);
            if (v < 28) {
                st_s[v] = ns;
                pr_s[v] = p;
                outb[t * V_ + v] = p;
            }
        }
        __syncthreads();
    }
}

// ---------------------------------------------------------------------------
extern "C" void kernel_launch(void* const* d_in, const int* in_sizes, int n_in,
                              void* d_out, int out_size)
{
    const float* x    = (const float*)d_in[0];
    const float* Wa   = (const float*)d_in[1];
    const float* Ua   = (const float*)d_in[2];
    const float* Va   = (const float*)d_in[3];
    const float* Ba1  = (const float*)d_in[4];
    const float* Ba2  = (const float*)d_in[5];
    /* Ba3 (d_in[6]) is softmax-invariant: skipped */
    const float* gk   = (const float*)d_in[7];
    const float* grk  = (const float*)d_in[8];
    const float* gb   = (const float*)d_in[9];
    const float* Wo   = (const float*)d_in[10];
    const float* Uo   = (const float*)d_in[11];
    const float* Co   = (const float*)d_in[12];
    const float* Bo   = (const float*)d_in[13];
    const float* emb  = (const float*)d_in[14];
    float* out = (float*)d_out;

    cudaFuncSetAttribute(recur_kernel, cudaFuncAttributeMaxDynamicSharedMemorySize, SMEM_FLOATS * 4);

    prep_w_kernel<<<NCp, 512>>>(Ua, gk, Co, Ba2, gb);
    gemm_kernel<<<dim3(150, 2), 256>>>(x);
    recur_kernel<<<B_, NTH, SMEM_FLOATS * 4>>>(Wa, Va, Ba1, grk, gb, Wo, Uo, Bo, emb, out);
}

// round 17
// speedup vs baseline: 1.1439x; 1.1065x over previous
#include <cuda_runtime.h>
#include <cuda_bf16.h>

// ---------------------------------------------------------------------------
// CascadedAttention: B=128, T=75, D=512, V=28
//
// Prologue v3 (bf16x3 tensor cores, ~2^-17 accuracy):
//   prep_w : W^T = [Ua | gk | Co | 0pad] split into bf16 hi + bf16 residual,
//            fragment-interleaved -> g_Bhi / g_Blo; + fused bias vector.
//   gemm   : [9600,512]@[512,640] -> g_scr via m16n8k16 bf16 mma,
//            3 terms (Ah*Bh + Ah*Bl + Al*Bh). A split in-registers from x.
// Recurrence: EXACT R4/R7/R13 known-good kernel (measured 269.5-274.3 us).
// ---------------------------------------------------------------------------

#define B_   128
#define T_   75
#define D_   512
#define V_   28
#define NCp  640               // padded scratch row (624 used + 16 pad)
#define PT   (T_*NCp)          // 48000 floats per batch row
#define M_   (B_*T_)           // 9600 flat rows

__device__ float          g_scr[M_ * NCp];   // 24.6 MB
__device__ __nv_bfloat16  g_Bhi[NCp * D_];   // 655 KB
__device__ __nv_bfloat16  g_Blo[NCp * D_];   // 655 KB
__device__ float          g_bias[NCp];

__device__ __forceinline__ float ex2f(float x){ float y; asm("ex2.approx.f32 %0, %1;" : "=f"(y) : "f"(x)); return y; }
__device__ __forceinline__ float rcpf(float x){ float y; asm("rcp.approx.f32 %0, %1;" : "=f"(y) : "f"(x)); return y; }
__device__ __forceinline__ float tanhf_hw(float x){ float y; asm("tanh.approx.f32 %0, %1;" : "=f"(y) : "f"(x)); return y; }
#define L2E 1.4426950408889634f
__device__ __forceinline__ float fast_sig(float x){ return fmaf(0.5f, tanhf_hw(0.5f * x), 0.5f); }

// split float2 -> bf16x2 hi (rn) + bf16x2 residual.  .b32 low half = v.x.
__device__ __forceinline__ void bf16split(float2 v, unsigned& h, unsigned& l){
    unsigned hp;
    asm("cvt.rn.bf16x2.f32 %0, %1, %2;" : "=r"(hp) : "f"(v.y), "f"(v.x)); // hi<=v.y, lo<=v.x
    float fx = __int_as_float(hp << 16);
    float fy = __int_as_float(hp & 0xffff0000u);
    float lx = v.x - fx;
    float ly = v.y - fy;
    unsigned lp;
    asm("cvt.rn.bf16x2.f32 %0, %1, %2;" : "=r"(lp) : "f"(ly), "f"(lx));
    h = hp; l = lp;
}

__device__ __forceinline__ void mma_bf16(float* d,
    unsigned a0, unsigned a1, unsigned a2, unsigned a3,
    unsigned b0, unsigned b1)
{
    asm volatile(
        "mma.sync.aligned.m16n8k16.row.col.f32.bf16.bf16.f32 "
        "{%0,%1,%2,%3}, {%4,%5,%6,%7}, {%8,%9}, {%0,%1,%2,%3};"
        : "+f"(d[0]), "+f"(d[1]), "+f"(d[2]), "+f"(d[3])
        : "r"(a0), "r"(a1), "r"(a2), "r"(a3), "r"(b0), "r"(b1));
}

// B-side slot->k map: within each 16-k group, slot rem = tg*4 + j holds
// k = 2*tg + (j&1) + ((j>>1)<<3), so (b0,b1) for thread tg is one .b64.
__device__ __forceinline__ int kmapB(int o){
    int g16 = o >> 4, rem = o & 15;
    int tg = rem >> 2, j = rem & 3;
    return g16 * 16 + 2 * tg + (j & 1) + ((j >> 1) << 3);
}

// ---------------------------------------------------------------------------
// prep_w: bf16 hi/lo split of W^T, fragment-interleaved; + g_bias.
// grid 640 x 512 threads.
// ---------------------------------------------------------------------------
__global__ void __launch_bounds__(512)
prep_w_kernel(const float* __restrict__ Ua,
              const float* __restrict__ gk,
              const float* __restrict__ Co,
              const float* __restrict__ Ba2,
              const float* __restrict__ gbias)
{
    int n = blockIdx.x;
    int o = threadIdx.x;
    int k = kmapB(o);
    float v = 0.0f;
    if (n < 512)      v = Ua[k * 512 + n];
    else if (n < 596) v = gk[k * 84 + (n - 512)];
    else if (n < 624) v = Co[k * 28 + (n - 596)];
    __nv_bfloat16 hb = __float2bfloat16_rn(v);
    float hf = __bfloat162float(hb);
    __nv_bfloat16 lb = __float2bfloat16_rn(v - hf);
    g_Bhi[n * D_ + o] = hb;
    g_Blo[n * D_ + o] = lb;
    if (o == 0) {
        float bv = 0.0f;
        if (n < 512)      bv = Ba2[n];
        else if (n < 596) bv = gbias[n - 512];
        g_bias[n] = bv;
    }
}

// ---------------------------------------------------------------------------
// gemm: grid (150, 2), 256 threads = 8 warps (2 M x 4 N).
// Warp tile 32x80: 2 m16-frags x 10 n8-frags, K=512 in 32 k16 steps, bf16x3.
// ---------------------------------------------------------------------------
__global__ void __launch_bounds__(256)
gemm_kernel(const float* __restrict__ x)
{
    const int lane = threadIdx.x & 31;
    const int w    = threadIdx.x >> 5;
    const int g    = lane >> 2;          // groupID
    const int tg   = lane & 3;           // threadID_in_group
    const int mw   = w & 1;
    const int nw   = w >> 1;
    const int m0   = blockIdx.x * 64 + mw * 32;
    const int n0   = blockIdx.y * 320 + nw * 80;

    const float* Ar = x + (long)(m0 + g) * D_;

    float acc[20][4];
    #pragma unroll
    for (int f = 0; f < 20; f++) {
        acc[f][0] = 0.f; acc[f][1] = 0.f; acc[f][2] = 0.f; acc[f][3] = 0.f;
    }

    for (int ko = 0; ko < D_; ko += 16) {
        // A fragments: mh0 rows (g, g+8), mh1 rows (g+16, g+24).
        // a0 = row0 k(2tg,2tg+1) ; a1 = row1 same ; a2 = row0 k(+8) ; a3 = row1 k(+8)
        unsigned Ah[8], Al[8];
        #pragma unroll
        for (int mh = 0; mh < 2; mh++) {
            const float* r0 = Ar + (mh * 16) * D_ + ko + 2 * tg;
            const float* r1 = r0 + 8 * D_;
            float2 v;
            v = *reinterpret_cast<const float2*>(r0);     bf16split(v, Ah[mh*4+0], Al[mh*4+0]);
            v = *reinterpret_cast<const float2*>(r1);     bf16split(v, Ah[mh*4+1], Al[mh*4+1]);
            v = *reinterpret_cast<const float2*>(r0 + 8); bf16split(v, Ah[mh*4+2], Al[mh*4+2]);
            v = *reinterpret_cast<const float2*>(r1 + 8); bf16split(v, Ah[mh*4+3], Al[mh*4+3]);
        }

        #pragma unroll
        for (int nt = 0; nt < 10; nt++) {
            const long boff = (long)(n0 + nt * 8 + g) * D_ + ko + tg * 4;
            uint2 bh = *reinterpret_cast<const uint2*>(&g_Bhi[boff]);
            uint2 bl = *reinterpret_cast<const uint2*>(&g_Blo[boff]);
            // m-half 0
            mma_bf16(acc[nt],      Ah[0], Ah[1], Ah[2], Ah[3], bh.x, bh.y);
            mma_bf16(acc[nt],      Ah[0], Ah[1], Ah[2], Ah[3], bl.x, bl.y);
            mma_bf16(acc[nt],      Al[0], Al[1], Al[2], Al[3], bh.x, bh.y);
            // m-half 1
            mma_bf16(acc[10 + nt], Ah[4], Ah[5], Ah[6], Ah[7], bh.x, bh.y);
            mma_bf16(acc[10 + nt], Ah[4], Ah[5], Ah[6], Ah[7], bl.x, bl.y);
            mma_bf16(acc[10 + nt], Al[4], Al[5], Al[6], Al[7], bh.x, bh.y);
        }
    }

    // epilogue: D rows (g, g+8, g+16, g+24), cols tg*2, tg*2+1 per n-frag
    #pragma unroll
    for (int nt = 0; nt < 10; nt++) {
        const int col = n0 + nt * 8 + tg * 2;
        float2 bs = *reinterpret_cast<const float2*>(g_bias + col);
        const long r0 = m0 + g;
        float2 v;
        v.x = acc[nt][0] + bs.x;      v.y = acc[nt][1] + bs.y;
        *reinterpret_cast<float2*>(g_scr + r0 * NCp + col) = v;
        v.x = acc[nt][2] + bs.x;      v.y = acc[nt][3] + bs.y;
        *reinterpret_cast<float2*>(g_scr + (r0 + 8) * NCp + col) = v;
        v.x = acc[10 + nt][0] + bs.x; v.y = acc[10 + nt][1] + bs.y;
        *reinterpret_cast<float2*>(g_scr + (r0 + 16) * NCp + col) = v;
        v.x = acc[10 + nt][2] + bs.x; v.y = acc[10 + nt][3] + bs.y;
        *reinterpret_cast<float2*>(g_scr + (r0 + 24) * NCp + col) = v;
    }
}

// ---------------------------------------------------------------------------
// Recurrence kernel (EXACT R4/R7/R13 known-good): 128 CTAs x 576 threads.
// ---------------------------------------------------------------------------
#define SMEM_FLOATS 56928
#define NTH 576

__global__ void __launch_bounds__(NTH)
recur_kernel(const float* __restrict__ Wa,
             const float* __restrict__ Va,
             const float* __restrict__ Ba1,
             const float* __restrict__ grk,
             const float* __restrict__ gbias,
             const float* __restrict__ Wo,
             const float* __restrict__ Uo,
             const float* __restrict__ Bo,
             const float* __restrict__ emb,
             float* __restrict__ out)
{
    extern __shared__ float smem[];
    float*        uah  = smem;                 // [75][512]
    float*        xgc  = smem + 38400;         // [75][112]
    unsigned int* wab  = reinterpret_cast<unsigned int*>(smem + 46800); // [28][256] bf16x2
    float*        va_s = smem + 53968;
    float*        ba1_s= smem + 54480;
    float*        uo_s = smem + 54992;
    float*        was_s= smem + 55776;
    float*        sc_s = smem + 56288;
    float*        xmc_s= smem + 56448;
    float*        hm_s = smem + 56560;
    float*        st_s = smem + 56648;
    float*        pr_s = smem + 56680;
    float*        woy_s= smem + 56712;
    float*        uoh_s= smem + 56744;
    float*        lut_s= smem + 56776;
    float*        b1_s = smem + 56808;
    float*        bo_s = smem + 56896;

    const int tid  = threadIdx.x;
    const int b    = blockIdx.x;
    const int lane = tid & 31;
    const int wid  = tid >> 5;

    // ---- bulk load precomputed UaH / XGC from scratch (stride 640, skip pad) ----
    const float4* src = reinterpret_cast<const float4*>(g_scr + (long)b * PT);
    for (int i = tid; i < PT/4; i += NTH) {
        float4 v = src[i];
        int base = i * 4;
        int t = base / NCp;
        int c = base - t * NCp;
        if (c < 512)      *reinterpret_cast<float4*>(&uah[t * 512 + c]) = v;
        else if (c < 624) *reinterpret_cast<float4*>(&xgc[t * 112 + (c - 512)]) = v;
    }
    // ---- params ----
    for (int i = tid; i < 512; i += NTH) { va_s[i] = Va[i]; ba1_s[i] = Ba1[i]; }
    for (int i = tid; i < 784; i += NTH) uo_s[i] = Uo[i];
    for (int i = tid; i < 28*256; i += NTH) {
        int r = i >> 8, c = i & 255;
        __nv_bfloat162 h;
        h.x = __float2bfloat16_rn(Wa[r * 512 + 2*c]);
        h.y = __float2bfloat16_rn(Wa[r * 512 + 2*c + 1]);
        wab[i] = *reinterpret_cast<unsigned int*>(&h);
    }
    if (tid < 84) b1_s[tid] = gbias[84 + tid];
    if (tid < 28) {
        bo_s[tid] = Bo[tid];
        float a = 0.0f;
        #pragma unroll
        for (int j = 0; j < 28; j++) a = fmaf(emb[tid * 28 + j], Wo[j], a);
        lut_s[tid] = a;
    }
    if (tid < 32) { st_s[tid] = 0.0f; pr_s[tid] = 0.0f; }
    __syncthreads();

    float va_r[16];
    #pragma unroll
    for (int i = 0; i < 16; i++) va_r[i] = va_s[lane + 32*i];

    float* outb = out + (long)b * T_ * V_;

    for (int t = 0; t < T_; t++) {
        // ---------- Phase A: state-only GEMVs, all in parallel ----------
        if (tid < 256) {
            float2 a = *reinterpret_cast<const float2*>(&ba1_s[2*tid]);
            #pragma unroll
            for (int v = 0; v < 28; v++) {
                float s = st_s[v];
                unsigned int w = wab[v * 256 + tid];
                float wx = __int_as_float(w << 16);
                float wy = __int_as_float(w & 0xffff0000u);
                a.x = fmaf(s, wx, a.x);
                a.y = fmaf(s, wy, a.y);
            }
            *reinterpret_cast<float2*>(&was_s[2*tid]) = a;
        } else if (tid < 340) {
            int g = tid - 256;              // hm: 84 outputs
            float a = b1_s[g];
            #pragma unroll
            for (int v = 0; v < 28; v++) a = fmaf(st_s[v], grk[v * 84 + g], a);
            hm_s[g] = a;
        } else if (wid == 11) {
            if (lane < 28) {                // uoh
                float a = 0.0f;
                #pragma unroll
                for (int u = 0; u < 28; u++) a = fmaf(st_s[u], uo_s[u * 28 + lane], a);
                uoh_s[lane] = a;
            }
        } else if (wid == 12) {
            if (lane < 28) {                // woy (embedding LUT on int(prev_pred))
                int ix = (int)pr_s[lane];
                ix = max(0, min(27, ix));
                woy_s[lane] = lut_s[ix];
            }
        }
        __syncthreads();

        // ---------- Phase B: scores, 18 warps, tanh.approx ----------
        {
            float ws_r[16];
            #pragma unroll
            for (int i = 0; i < 16; i++) ws_r[i] = was_s[lane + 32*i];

            for (int r = wid; r < T_; r += 18) {
                const float* up = &uah[r * 512];
                float acc0 = 0.0f, acc1 = 0.0f;
                #pragma unroll
                for (int i = 0; i < 16; i += 2) {
                    float th0 = tanhf_hw(up[lane + 32*i]     + ws_r[i]);
                    float th1 = tanhf_hw(up[lane + 32*(i+1)] + ws_r[i+1]);
                    acc0 = fmaf(th0, va_r[i],   acc0);
                    acc1 = fmaf(th1, va_r[i+1], acc1);
                }
                float acc = acc0 + acc1;
                #pragma unroll
                for (int o = 16; o; o >>= 1) acc += __shfl_xor_sync(0xffffffffu, acc, o);
                if (lane == 0) sc_s[r] = acc;
            }
        }
        __syncthreads();

        // ---------- Phase C: softmax-in-registers + sm.XGC (warps 0-3) ----------
        if (wid < 4) {
            float s0 = sc_s[lane];
            float s1 = sc_s[lane + 32];
            float s2 = (lane < 11) ? sc_s[lane + 64] : -3.0e38f;
            float m = fmaxf(fmaxf(s0, s1), s2);
            #pragma unroll
            for (int o = 16; o; o >>= 1) m = fmaxf(m, __shfl_xor_sync(0xffffffffu, m, o));
            float e0 = ex2f((s0 - m) * L2E);
            float e1 = ex2f((s1 - m) * L2E);
            float e2 = (lane < 11) ? ex2f((s2 - m) * L2E) : 0.0f;
            float sum = e0 + e1 + e2;
            #pragma unroll
            for (int o = 16; o; o >>= 1) sum += __shfl_xor_sync(0xffffffffu, sum, o);
            float inv = rcpf(sum);

            int c = wid * 28 + ((lane < 28) ? lane : 0);   // 112 cols; lanes 28-31 duplicate
            float a0 = 0.0f, a1 = 0.0f, a2 = 0.0f, a3 = 0.0f;
            #pragma unroll
            for (int k = 0; k < 75; k += 4) {
                float w0 = __shfl_sync(0xffffffffu, (k      < 32) ? e0 : ((k      < 64) ? e1 : e2), k      & 31);
                a0 = fmaf(w0, xgc[k * 112 + c], a0);
                if (k + 1 < 75) {
                    float w1 = __shfl_sync(0xffffffffu, (k+1 < 32) ? e0 : ((k+1 < 64) ? e1 : e2), (k+1) & 31);
                    a1 = fmaf(w1, xgc[(k+1) * 112 + c], a1);
                }
                if (k + 2 < 75) {
                    float w2 = __shfl_sync(0xffffffffu, (k+2 < 32) ? e0 : ((k+2 < 64) ? e1 : e2), (k+2) & 31);
                    a2 = fmaf(w2, xgc[(k+2) * 112 + c], a2);
                }
                if (k + 3 < 75) {
                    float w3 = __shfl_sync(0xffffffffu, (k+3 < 32) ? e0 : ((k+3 < 64) ? e1 : e2), (k+3) & 31);
                    a3 = fmaf(w3, xgc[(k+3) * 112 + c], a3);
                }
            }
            if (lane < 28) xmc_s[c] = ((a0 + a1) + (a2 + a3)) * inv;
        }
        __syncthreads();

        // ---------- Phase D: GRU gates + output softmax (warp 0) ----------
        if (wid == 0) {
            int v = lane;
            float logit = -3.0e38f;
            float ns = 0.0f;
            if (v < 28) {
                float xz = xmc_s[v],      xr = xmc_s[28 + v], xh  = xmc_s[56 + v];
                float hz = hm_s[v],       hr = hm_s[28 + v],  hh_ = hm_s[56 + v];
                float z  = fast_sig(xz + hz);
                float r  = fast_sig(xr + hr);
                float hh = tanhf_hw(fmaf(r, hh_, xh));
                float st = st_s[v];
                ns = fmaf(z, st - hh, hh);
                logit = ((woy_s[v] + uoh_s[v]) + (xmc_s[84 + v] + bo_s[v]));
            }
            float m = logit;
            #pragma unroll
            for (int o = 16; o; o >>= 1) m = fmaxf(m, __shfl_xor_sync(0xffffffffu, m, o));
            float e = (v < 28) ? ex2f((logit - m) * L2E) : 0.0f;
            float sum = e;
            #pragma unroll
            for (int o = 16; o; o >>= 1) sum += __shfl_xor_sync(0xffffffffu, sum, o);
            float p = e * rcpf(sum);
            if (v < 28) {
                st_s[v] = ns;
                pr_s[v] = p;
                outb[t * V_ + v] = p;
            }
        }
        __syncthreads();
    }
}

// ---------------------------------------------------------------------------
extern "C" void kernel_launch(void* const* d_in, const int* in_sizes, int n_in,
                              void* d_out, int out_size)
{
    const float* x    = (const float*)d_in[0];
    const float* Wa   = (const float*)d_in[1];
    const float* Ua   = (const float*)d_in[2];
    const float* Va   = (const float*)d_in[3];
    const float* Ba1  = (const float*)d_in[4];
    const float* Ba2  = (const float*)d_in[5];
    /* Ba3 (d_in[6]) is softmax-invariant: skipped */
    const float* gk   = (const float*)d_in[7];
    const float* grk  = (const float*)d_in[8];
    const float* gb   = (const float*)d_in[9];
    const float* Wo   = (const float*)d_in[10];
    const float* Uo   = (const float*)d_in[11];
    const float* Co   = (const float*)d_in[12];
    const float* Bo   = (const float*)d_in[13];
    const float* emb  = (const float*)d_in[14];
    float* out = (float*)d_out;

    cudaFuncSetAttribute(recur_kernel, cudaFuncAttributeMaxDynamicSharedMemorySize, SMEM_FLOATS * 4);

    prep_w_kernel<<<NCp, 512>>>(Ua, gk, Co, Ba2, gb);
    gemm_kernel<<<dim3(150, 2), 256>>>(x);
    recur_kernel<<<B_, NTH, SMEM_FLOATS * 4>>>(Wa, Va, Ba1, grk, gb, Wo, Uo, Bo, emb, out);
}